// round 15
// baseline (speedup 1.0000x reference)
#include <cuda_runtime.h>
#include <cuda.h>
#include <cuda_fp16.h>
#include <cstdint>
#include <cstddef>

#define TOKENS 8192
#define DIN    4096
#define DOUT   4096

// ---------------- scratch (allocation-free: device globals) ----------------
__device__ __align__(1024) __half g_B[(size_t)DOUT * DIN];     // W^T in fp16, [N,K]

// ---------------- helpers (defined before use) ----------------
__device__ __forceinline__ uint32_t h2_as_u32(__half2 h) {
    return *reinterpret_cast<uint32_t*>(&h);
}
__device__ __forceinline__ uint32_t smem_u32(const void* p) {
    uint32_t a;
    asm("{ .reg .u64 t; cvta.to.shared.u64 t, %1; cvt.u32.u64 %0, t; }" : "=r"(a) : "l"(p));
    return a;
}
__device__ __forceinline__ void mbar_init(uint32_t mbar, uint32_t cnt) {
    asm volatile("mbarrier.init.shared.b64 [%0], %1;" :: "r"(mbar), "r"(cnt) : "memory");
}
__device__ __forceinline__ void mbar_arrive(uint32_t mbar) {
    asm volatile("mbarrier.arrive.shared.b64 _, [%0];" :: "r"(mbar) : "memory");
}
__device__ __forceinline__ void mbar_arrive_expect(uint32_t mbar, uint32_t bytes) {
    asm volatile("mbarrier.arrive.expect_tx.shared.b64 _, [%0], %1;" :: "r"(mbar), "r"(bytes) : "memory");
}
__device__ __forceinline__ void mbar_wait(uint32_t mbar, uint32_t parity) {
    asm volatile(
        "{\n\t.reg .pred P;\n\t"
        "WL_%=:\n\t"
        "mbarrier.try_wait.parity.acquire.cta.shared::cta.b64 P, [%0], %1, 0x989680;\n\t"
        "@P bra.uni WD_%=;\n\t"
        "bra.uni WL_%=;\n\t"
        "WD_%=:\n\t}"
        :: "r"(mbar), "r"(parity) : "memory");
}
__device__ __forceinline__ void tma3d(uint32_t dst, const CUtensorMap* map,
                                      int cx, int cy, uint32_t mbar) {
    asm volatile(
        "cp.async.bulk.tensor.3d.shared::cta.global.tile.mbarrier::complete_tx::bytes "
        "[%0], [%1, {%2, %3, %4}], [%5];"
        :: "r"(dst), "l"(map), "r"(cx), "r"(cy), "r"(0), "r"(mbar) : "memory");
}
__device__ __forceinline__ void ldsm4(uint32_t* r, uint32_t addr) {
    asm volatile("ldmatrix.sync.aligned.m8n8.x4.shared.b16 {%0,%1,%2,%3}, [%4];"
                 : "=r"(r[0]), "=r"(r[1]), "=r"(r[2]), "=r"(r[3]) : "r"(addr));
}
__device__ __forceinline__ void mma16816(float* d, const uint32_t* a, const uint32_t* b) {
    asm volatile(
        "mma.sync.aligned.m16n8k16.row.col.f32.f16.f16.f32 "
        "{%0,%1,%2,%3}, {%4,%5,%6,%7}, {%8,%9}, {%0,%1,%2,%3};"
        : "+f"(d[0]), "+f"(d[1]), "+f"(d[2]), "+f"(d[3])
        : "r"(a[0]), "r"(a[1]), "r"(a[2]), "r"(a[3]), "r"(b[0]), "r"(b[1]));
}

// ---------------- W-only conversion kernel (x handled in-GEMM) ----------------
static constexpr int WB = 2048;

__global__ void __launch_bounds__(256)
conv_w(const int* __restrict__ W) {
    const int tid = threadIdx.x;
    __shared__ __half t[32][33];
    const int tx = tid & 31;
    const int ty = tid >> 5;
    const int wtiles = (DIN / 32) * (DOUT / 32);
    for (int tt = blockIdx.x; tt < wtiles; tt += WB) {
        int tn = tt & 127, tk = tt >> 7;
        int n0 = tn * 32, k0 = tk * 32;
        __syncthreads();
#pragma unroll
        for (int j = 0; j < 32; j += 8)
            t[ty + j][tx] = __int2half_rn(__ldcs(&W[(size_t)(k0 + ty + j) * DOUT + (n0 + tx)]));
        __syncthreads();
#pragma unroll
        for (int j = 0; j < 32; j += 8)
            g_B[(size_t)(n0 + ty + j) * DIN + (k0 + tx)] = t[tx][ty + j];
    }
}

// ---------------- persistent GEMM: CTA 128x256x64, S=3, A loaded f32 + in-smem convert ----------------
static constexpr int NCTA = 148;
static constexpr int BM = 128, BN = 256, BK = 64;
static constexpr int S = 3;
static constexpr int KT = DIN / BK;                         // 64
static constexpr int NTILES = (TOKENS / BM) * (DOUT / BN);  // 1024
static constexpr uint32_t A32PANEL = BM * 32 * 4;           // 16384 (32 f32 cols, SW128)
static constexpr uint32_t A32BYTES = 2 * A32PANEL;          // 32768
static constexpr uint32_t BBYTES   = BN * BK * 2;           // 32768
static constexpr uint32_t STAGE    = A32BYTES + BBYTES;     // 65536
static constexpr uint32_t TXB      = STAGE;
static constexpr uint32_t A16BYTES = BM * BK * 2;           // 16384 = f16 A tile (R13 bug: was /2)
static constexpr uint32_t SMEM_BYTES = 1024 + S * STAGE + 2 * A16BYTES + 256;  // 230656 B

__device__ __forceinline__ void tile_coords(int t, int& m0, int& n0) {
    int grp = t >> 7, r = t & 127;
    m0 = (grp * 8 + (r & 7)) * BM;
    n0 = (r >> 3) * BN;
}

__global__ void __launch_bounds__(256, 1)
gemm_persist(const __grid_constant__ CUtensorMap tmA32,
             const __grid_constant__ CUtensorMap tmB,
             float* __restrict__ out) {
    extern __shared__ char smem[];
    const uint32_t sb      = smem_u32(smem);
    const uint32_t tiles   = (sb + 1023u) & ~1023u;
    const uint32_t a16base = tiles + S * STAGE;
    const uint32_t bar     = a16base + 2 * A16BYTES;
#define FULL(s)  (bar + (uint32_t)(s) * 16u)
#define EMPTY(s) (bar + (uint32_t)(s) * 16u + 8u)

    const int tid  = threadIdx.x;
    const int lane = tid & 31;
    const int wid  = tid >> 5;
    const int bid  = blockIdx.x;

    if (tid == 0) {
#pragma unroll
        for (int s = 0; s < S; s++) { mbar_init(FULL(s), 1); mbar_init(EMPTY(s), 8); }
    }
    __syncthreads();

    const int ntl   = (NTILES - bid + NCTA - 1) / NCTA;
    const int total = ntl * KT;

    // ldmatrix swizzled offsets (A relative to a16 buffer, B relative to stage base)
    const int wm = wid & 1, wn = wid >> 1;
    const int gq = lane >> 3;
    const uint32_t swz = (uint32_t)(lane & 7) << 4;
    uint32_t offA[4], offB[4];
#pragma unroll
    for (int i = 0; i < 4; i++) {
        int row = wm * 64 + i * 16 + (gq & 1) * 8 + (lane & 7);
        offA[i] = (uint32_t)row * 128u;
    }
#pragma unroll
    for (int j = 0; j < 4; j++) {
        int row = wn * 64 + j * 16 + (gq >> 1) * 8 + (lane & 7);
        offB[j] = A32BYTES + (uint32_t)row * 128u;
    }
    const uint32_t selA = (uint32_t)(gq >> 1) * 16u;
    const uint32_t selB = (uint32_t)(gq & 1) * 16u;

    float acc[4][8][4];
#pragma unroll
    for (int i = 0; i < 4; i++)
#pragma unroll
        for (int j = 0; j < 8; j++)
#pragma unroll
            for (int v = 0; v < 4; v++) acc[i][j][v] = 0.f;

    // producer cursor (R11-proven parity logic: fresh EMPTY passes with phase 1)
    int ps = 0, pph = 1;
    auto fillq = [&](int q) {
        mbar_wait(EMPTY(ps), (uint32_t)pph);
        int t = bid + (q >> 6) * NCTA;
        int m0, n0; tile_coords(t, m0, n0);
        int kx = (q & (KT - 1)) * BK;      // f32 element coordinate
        uint32_t base = tiles + (uint32_t)ps * STAGE;
        mbar_arrive_expect(FULL(ps), TXB);
        tma3d(base,            &tmA32, kx,      m0, FULL(ps));
        tma3d(base + A32PANEL, &tmA32, kx + 32, m0, FULL(ps));
        tma3d(base + A32BYTES, &tmB,   kx,      n0, FULL(ps));
        if (++ps == S) { ps = 0; pph ^= 1; }
    };

    if (tid == 0) {
#pragma unroll
        for (int q = 0; q < S - 1; q++) if (q < total) fillq(q);
    }

    int cs = 0, cph = 0;   // consumer cursor

#pragma unroll 1
    for (int i = 0; i < total; i++) {
        if (tid == 0) {
            const int q = i + S - 1;
            if (q < total) fillq(q);
        }

        mbar_wait(FULL(cs), (uint32_t)cph);
        const uint32_t base = tiles + (uint32_t)cs * STAGE;
        const uint32_t a16  = a16base + (uint32_t)(i & 1) * A16BYTES;

        // ---- convert f32 A tile (swizzled panels) -> f16 A tile (swizzled) ----
        // race-free ping-pong: writers at iter i+1 touch buffer (i+1)&1 while the
        // slowest warp is still in MMA(i) reading buffer i&1; the per-iteration
        // __syncthreads below bounds the skew to one iteration.
#pragma unroll
        for (int t2 = 0; t2 < 4; t2++) {
            const int task = t2 * 256 + tid;
            const uint32_t r = (uint32_t)(task >> 3);
            const uint32_t c = (uint32_t)(task & 7);
            const uint32_t sw = (r & 7u) << 4;
            const uint32_t srcp = base + (c >> 2) * A32PANEL + r * 128u;
            const uint32_t s0 = srcp + (((c & 3u) * 32u) ^ sw);
            const uint32_t s1 = srcp + (((c & 3u) * 32u + 16u) ^ sw);
            float4 f0, f1;
            asm volatile("ld.shared.v4.f32 {%0,%1,%2,%3}, [%4];"
                         : "=f"(f0.x), "=f"(f0.y), "=f"(f0.z), "=f"(f0.w) : "r"(s0));
            asm volatile("ld.shared.v4.f32 {%0,%1,%2,%3}, [%4];"
                         : "=f"(f1.x), "=f"(f1.y), "=f"(f1.z), "=f"(f1.w) : "r"(s1));
            uint32_t o0 = h2_as_u32(__floats2half2_rn(f0.x, f0.y));
            uint32_t o1 = h2_as_u32(__floats2half2_rn(f0.z, f0.w));
            uint32_t o2 = h2_as_u32(__floats2half2_rn(f1.x, f1.y));
            uint32_t o3 = h2_as_u32(__floats2half2_rn(f1.z, f1.w));
            const uint32_t dst = a16 + r * 128u + ((c * 16u) ^ sw);
            asm volatile("st.shared.v4.b32 [%0], {%1,%2,%3,%4};"
                         :: "r"(dst), "r"(o0), "r"(o1), "r"(o2), "r"(o3) : "memory");
        }
        __syncthreads();

        // ---- MMA over BK=64 (A from a16 buffer, B from stage) ----
#pragma unroll
        for (int ks = 0; ks < 4; ks++) {
            const uint32_t ckA = (((uint32_t)ks * 2u) * 16u + selA) ^ swz;
            const uint32_t ckB = (((uint32_t)ks * 2u) * 16u + selB) ^ swz;
            uint32_t a[4][4], b[4][4];
#pragma unroll
            for (int ii = 0; ii < 4; ii++) ldsm4(a[ii], a16 + offA[ii] + ckA);
#pragma unroll
            for (int jj = 0; jj < 4; jj++) ldsm4(b[jj], base + offB[jj] + ckB);
#pragma unroll
            for (int ii = 0; ii < 4; ii++)
#pragma unroll
                for (int jj = 0; jj < 4; jj++) {
                    mma16816(acc[ii][2 * jj],     a[ii], &b[jj][0]);
                    mma16816(acc[ii][2 * jj + 1], a[ii], &b[jj][2]);
                }
        }
        if (lane == 0) mbar_arrive(EMPTY(cs));
        if (++cs == S) { cs = 0; cph ^= 1; }

        if ((i & (KT - 1)) == KT - 1) {
            int t = bid + (i >> 6) * NCTA;
            int m0, n0; tile_coords(t, m0, n0);
            const int mrow = m0 + wm * 64 + (lane >> 2);
            const int ncol = n0 + wn * 64 + (lane & 3) * 2;
#pragma unroll
            for (int ii = 0; ii < 4; ii++) {
#pragma unroll
                for (int jn = 0; jn < 8; jn++) {
                    float2 v0 = make_float2(acc[ii][jn][0], acc[ii][jn][1]);
                    float2 v1 = make_float2(acc[ii][jn][2], acc[ii][jn][3]);
                    *reinterpret_cast<float2*>(out + (size_t)(mrow + ii * 16) * DOUT + ncol + jn * 8)     = v0;
                    *reinterpret_cast<float2*>(out + (size_t)(mrow + ii * 16 + 8) * DOUT + ncol + jn * 8) = v1;
#pragma unroll
                    for (int v = 0; v < 4; v++) acc[ii][jn][v] = 0.f;
                }
            }
        }
    }
#undef FULL
#undef EMPTY
}

// ---------------- host launch ----------------
typedef CUresult (*encode_fn_t)(CUtensorMap*, CUtensorMapDataType, cuuint32_t, void*,
                                const cuuint64_t*, const cuuint64_t*, const cuuint32_t*,
                                const cuuint32_t*, CUtensorMapInterleave, CUtensorMapSwizzle,
                                CUtensorMapL2promotion, CUtensorMapFloatOOBfill);

extern "C" void kernel_launch(void* const* d_in, const int* in_sizes, int n_in,
                              void* d_out, int out_size) {
    const float* x = (const float*)d_in[0];
    const int*   W = (const int*)d_in[1];
    float* out = (float*)d_out;

    void* pb = nullptr;
    cudaGetSymbolAddress(&pb, g_B);

    static encode_fn_t enc = nullptr;
    if (!enc) {
        cudaDriverEntryPointQueryResult st;
        cudaGetDriverEntryPointByVersion("cuTensorMapEncodeTiled", (void**)&enc,
                                         12000, cudaEnableDefault, &st);
    }
    CUtensorMap mA32{}, mB{};
    {
        // x directly as f32: [DIN, TOKENS], box 32x128 (128B inner = SW128 atom)
        cuuint64_t dims[3] = {DIN, TOKENS, 1};
        cuuint64_t str[2]  = {DIN * 4ull, (cuuint64_t)TOKENS * DIN * 4ull};
        cuuint32_t box[3]  = {32, 128, 1};
        cuuint32_t es[3]   = {1, 1, 1};
        enc(&mA32, CU_TENSOR_MAP_DATA_TYPE_FLOAT32, 3, (void*)x, dims, str, box, es,
            CU_TENSOR_MAP_INTERLEAVE_NONE, CU_TENSOR_MAP_SWIZZLE_128B,
            CU_TENSOR_MAP_L2_PROMOTION_L2_128B, CU_TENSOR_MAP_FLOAT_OOB_FILL_NONE);
    }
    {
        cuuint64_t dims[3] = {DIN, DOUT, 1};
        cuuint64_t str[2]  = {DIN * 2ull, (cuuint64_t)DOUT * DIN * 2ull};
        cuuint32_t box[3]  = {64, 256, 1};
        cuuint32_t es[3]   = {1, 1, 1};
        enc(&mB, CU_TENSOR_MAP_DATA_TYPE_FLOAT16, 3, pb, dims, str, box, es,
            CU_TENSOR_MAP_INTERLEAVE_NONE, CU_TENSOR_MAP_SWIZZLE_128B,
            CU_TENSOR_MAP_L2_PROMOTION_L2_128B, CU_TENSOR_MAP_FLOAT_OOB_FILL_NONE);
    }

    // 1) W -> fp16 transposed (x conversion fused into the GEMM)
    conv_w<<<WB, 256>>>(W);

    // 2) persistent GEMM
    cudaFuncSetAttribute(gemm_persist, cudaFuncAttributeMaxDynamicSharedMemorySize, SMEM_BYTES);
    gemm_persist<<<NCTA, 256, SMEM_BYTES>>>(mA32, mB, out);
}

// round 16
// speedup vs baseline: 1.4311x; 1.4311x over previous
#include <cuda_runtime.h>
#include <cuda.h>
#include <cuda_fp16.h>
#include <cstdint>
#include <cstddef>

#define TOKENS 8192
#define DIN    4096
#define DOUT   4096

// ---------------- scratch (allocation-free: device globals) ----------------
__device__ __align__(1024) __half g_A[(size_t)TOKENS * DIN];   // x in fp16, [M,K]
__device__ __align__(1024) __half g_B[(size_t)DOUT * DIN];     // W^T in fp16, [N,K]

// ---------------- helpers (defined before use) ----------------
__device__ __forceinline__ uint32_t h2_as_u32(__half2 h) {
    return *reinterpret_cast<uint32_t*>(&h);
}
__device__ __forceinline__ uint32_t smem_u32(const void* p) {
    uint32_t a;
    asm("{ .reg .u64 t; cvta.to.shared.u64 t, %1; cvt.u32.u64 %0, t; }" : "=r"(a) : "l"(p));
    return a;
}
__device__ __forceinline__ void mbar_init(uint32_t mbar, uint32_t cnt) {
    asm volatile("mbarrier.init.shared.b64 [%0], %1;" :: "r"(mbar), "r"(cnt) : "memory");
}
__device__ __forceinline__ void mbar_arrive(uint32_t mbar) {
    asm volatile("mbarrier.arrive.shared.b64 _, [%0];" :: "r"(mbar) : "memory");
}
__device__ __forceinline__ void mbar_arrive_expect(uint32_t mbar, uint32_t bytes) {
    asm volatile("mbarrier.arrive.expect_tx.shared.b64 _, [%0], %1;" :: "r"(mbar), "r"(bytes) : "memory");
}
__device__ __forceinline__ void mbar_wait(uint32_t mbar, uint32_t parity) {
    asm volatile(
        "{\n\t.reg .pred P;\n\t"
        "WL_%=:\n\t"
        "mbarrier.try_wait.parity.acquire.cta.shared::cta.b64 P, [%0], %1, 0x989680;\n\t"
        "@P bra.uni WD_%=;\n\t"
        "bra.uni WL_%=;\n\t"
        "WD_%=:\n\t}"
        :: "r"(mbar), "r"(parity) : "memory");
}
__device__ __forceinline__ void tma3d(uint32_t dst, const CUtensorMap* map,
                                      int cx, int cy, uint32_t mbar) {
    asm volatile(
        "cp.async.bulk.tensor.3d.shared::cta.global.tile.mbarrier::complete_tx::bytes "
        "[%0], [%1, {%2, %3, %4}], [%5];"
        :: "r"(dst), "l"(map), "r"(cx), "r"(cy), "r"(0), "r"(mbar) : "memory");
}
__device__ __forceinline__ void ldsm4(uint32_t* r, uint32_t addr) {
    asm volatile("ldmatrix.sync.aligned.m8n8.x4.shared.b16 {%0,%1,%2,%3}, [%4];"
                 : "=r"(r[0]), "=r"(r[1]), "=r"(r[2]), "=r"(r[3]) : "r"(addr));
}
__device__ __forceinline__ void mma16816(float* d, const uint32_t* a, const uint32_t* b) {
    asm volatile(
        "mma.sync.aligned.m16n8k16.row.col.f32.f16.f16.f32 "
        "{%0,%1,%2,%3}, {%4,%5,%6,%7}, {%8,%9}, {%0,%1,%2,%3};"
        : "+f"(d[0]), "+f"(d[1]), "+f"(d[2]), "+f"(d[3])
        : "r"(a[0]), "r"(a[1]), "r"(a[2]), "r"(a[3]), "r"(b[0]), "r"(b[1]));
}

// ---------------- merged conversion kernel ----------------
// x and W are read-once: stream them through L2 (__ldcs) so the A/B writes
// (read soon by the GEMM) keep L2 residency.
static constexpr int XB = 2048;
static constexpr int WB = 2048;

__global__ void __launch_bounds__(256)
conv_all(const float4* __restrict__ x, const int* __restrict__ W) {
    const int tid = threadIdx.x;
    if (blockIdx.x < XB) {
        uint4* dst = reinterpret_cast<uint4*>(g_A);
        const size_t n4 = (size_t)TOKENS * DIN / 8;
        const size_t stride = (size_t)XB * 256;
        size_t i = (size_t)blockIdx.x * 256 + tid;
#pragma unroll 2
        for (; i < n4; i += stride) {
            float4 v0 = __ldcs(&x[2 * i]);
            float4 v1 = __ldcs(&x[2 * i + 1]);
            uint4 o;
            o.x = h2_as_u32(__floats2half2_rn(v0.x, v0.y));
            o.y = h2_as_u32(__floats2half2_rn(v0.z, v0.w));
            o.z = h2_as_u32(__floats2half2_rn(v1.x, v1.y));
            o.w = h2_as_u32(__floats2half2_rn(v1.z, v1.w));
            dst[i] = o;
        }
    } else {
        __shared__ __half t[32][33];
        const int tx = tid & 31;
        const int ty = tid >> 5;
        const int wtiles = (DIN / 32) * (DOUT / 32);
        for (int tt = blockIdx.x - XB; tt < wtiles; tt += WB) {
            int tn = tt & 127, tk = tt >> 7;
            int n0 = tn * 32, k0 = tk * 32;
            __syncthreads();
#pragma unroll
            for (int j = 0; j < 32; j += 8)
                t[ty + j][tx] = __int2half_rn(__ldcs(&W[(size_t)(k0 + ty + j) * DOUT + (n0 + tx)]));
            __syncthreads();
#pragma unroll
            for (int j = 0; j < 32; j += 8)
                g_B[(size_t)(n0 + ty + j) * DIN + (k0 + tx)] = t[tx][ty + j];
        }
    }
}

// ---------------- persistent GEMM: CTA 128x256x64, S=4 (proven best config) ----------------
static constexpr int NCTA = 148;
static constexpr int BM = 128, BN = 256, BK = 64;
static constexpr int S = 4;
static constexpr int KT = DIN / BK;                         // 64
static constexpr int NTILES = (TOKENS / BM) * (DOUT / BN);  // 1024
static constexpr uint32_t ABYTES = BM * BK * 2;             // 16384
static constexpr uint32_t BBYTES = BN * BK * 2;             // 32768
static constexpr uint32_t STAGE  = ABYTES + BBYTES;         // 49152
static constexpr uint32_t TXB    = STAGE;
static constexpr uint32_t SMEM_BYTES = S * STAGE + 1024 + 128;

__device__ __forceinline__ void tile_coords(int t, int& m0, int& n0) {
    int grp = t >> 7, r = t & 127;
    m0 = (grp * 8 + (r & 7)) * BM;
    n0 = (r >> 3) * BN;
}

__global__ void __launch_bounds__(256, 1)
gemm_persist(const __grid_constant__ CUtensorMap tmA,
             const __grid_constant__ CUtensorMap tmB,
             float* __restrict__ out) {
    extern __shared__ char smem[];
    const uint32_t sb    = smem_u32(smem);
    const uint32_t tiles = (sb + 1023u) & ~1023u;
    const uint32_t bar   = tiles + S * STAGE;
#define FULL(s)  (bar + (uint32_t)(s) * 16u)
#define EMPTY(s) (bar + (uint32_t)(s) * 16u + 8u)

    const int tid  = threadIdx.x;
    const int lane = tid & 31;
    const int wid  = tid >> 5;
    const int bid  = blockIdx.x;

    if (tid == 0) {
#pragma unroll
        for (int s = 0; s < S; s++) { mbar_init(FULL(s), 1); mbar_init(EMPTY(s), 8); }
    }
    __syncthreads();

    const int ntl   = (NTILES - bid + NCTA - 1) / NCTA;
    const int total = ntl * KT;

    const int wm = wid & 1, wn = wid >> 1;
    const int gq = lane >> 3;
    const uint32_t swz = (uint32_t)(lane & 7) << 4;
    uint32_t offA[4], offB[4];
#pragma unroll
    for (int i = 0; i < 4; i++) {
        int row = wm * 64 + i * 16 + (gq & 1) * 8 + (lane & 7);
        offA[i] = (uint32_t)row * 128u;
    }
#pragma unroll
    for (int j = 0; j < 4; j++) {
        int row = wn * 64 + j * 16 + (gq >> 1) * 8 + (lane & 7);
        offB[j] = ABYTES + (uint32_t)row * 128u;
    }
    const uint32_t selA = (uint32_t)(gq >> 1) * 16u;
    const uint32_t selB = (uint32_t)(gq & 1) * 16u;

    float acc[4][8][4];
#pragma unroll
    for (int i = 0; i < 4; i++)
#pragma unroll
        for (int j = 0; j < 8; j++)
#pragma unroll
            for (int v = 0; v < 4; v++) acc[i][j][v] = 0.f;

    auto fillq = [&](int q) {
        int t = bid + (q >> 6) * NCTA;
        int m0, n0; tile_coords(t, m0, n0);
        int kb = q & (KT - 1);
        int s  = q & (S - 1);
        uint32_t base = tiles + (uint32_t)s * STAGE;
        mbar_arrive_expect(FULL(s), TXB);
        tma3d(base,          &tmA, kb * BK, m0, FULL(s));
        tma3d(base + ABYTES, &tmB, kb * BK, n0, FULL(s));
    };

    if (tid == 0) {
#pragma unroll
        for (int q = 0; q < S - 1; q++) if (q < total) fillq(q);
    }

#pragma unroll 1
    for (int i = 0; i < total; i++) {
        const int s = i & (S - 1);

        if (tid == 0) {
            const int q = i + S - 1;
            if (q < total) {
                if (q >= S) mbar_wait(EMPTY(q & (S - 1)), ((uint32_t)(q >> 2) + 1u) & 1u);
                fillq(q);
            }
        }

        mbar_wait(FULL(s), (uint32_t)(i >> 2) & 1u);
        const uint32_t base = tiles + (uint32_t)s * STAGE;

#pragma unroll
        for (int ks = 0; ks < 4; ks++) {
            const uint32_t ckA = (((uint32_t)ks * 2u) * 16u + selA) ^ swz;
            const uint32_t ckB = (((uint32_t)ks * 2u) * 16u + selB) ^ swz;
            uint32_t a[4][4], b[4][4];
#pragma unroll
            for (int ii = 0; ii < 4; ii++) ldsm4(a[ii], base + offA[ii] + ckA);
#pragma unroll
            for (int jj = 0; jj < 4; jj++) ldsm4(b[jj], base + offB[jj] + ckB);
#pragma unroll
            for (int ii = 0; ii < 4; ii++)
#pragma unroll
                for (int jj = 0; jj < 4; jj++) {
                    mma16816(acc[ii][2 * jj],     a[ii], &b[jj][0]);
                    mma16816(acc[ii][2 * jj + 1], a[ii], &b[jj][2]);
                }
        }
        if (lane == 0) mbar_arrive(EMPTY(s));

        if ((i & (KT - 1)) == KT - 1) {
            int t = bid + (i >> 6) * NCTA;
            int m0, n0; tile_coords(t, m0, n0);
            const int mrow = m0 + wm * 64 + (lane >> 2);
            const int ncol = n0 + wn * 64 + (lane & 3) * 2;
#pragma unroll
            for (int ii = 0; ii < 4; ii++) {
#pragma unroll
                for (int jn = 0; jn < 8; jn++) {
                    float2 v0 = make_float2(acc[ii][jn][0], acc[ii][jn][1]);
                    float2 v1 = make_float2(acc[ii][jn][2], acc[ii][jn][3]);
                    *reinterpret_cast<float2*>(out + (size_t)(mrow + ii * 16) * DOUT + ncol + jn * 8)     = v0;
                    *reinterpret_cast<float2*>(out + (size_t)(mrow + ii * 16 + 8) * DOUT + ncol + jn * 8) = v1;
#pragma unroll
                    for (int v = 0; v < 4; v++) acc[ii][jn][v] = 0.f;
                }
            }
        }
    }
#undef FULL
#undef EMPTY
}

// ---------------- host launch ----------------
typedef CUresult (*encode_fn_t)(CUtensorMap*, CUtensorMapDataType, cuuint32_t, void*,
                                const cuuint64_t*, const cuuint64_t*, const cuuint32_t*,
                                const cuuint32_t*, CUtensorMapInterleave, CUtensorMapSwizzle,
                                CUtensorMapL2promotion, CUtensorMapFloatOOBfill);

extern "C" void kernel_launch(void* const* d_in, const int* in_sizes, int n_in,
                              void* d_out, int out_size) {
    const float* x = (const float*)d_in[0];
    const int*   W = (const int*)d_in[1];
    float* out = (float*)d_out;

    void* pa = nullptr; void* pb = nullptr;
    cudaGetSymbolAddress(&pa, g_A);
    cudaGetSymbolAddress(&pb, g_B);

    static encode_fn_t enc = nullptr;
    if (!enc) {
        cudaDriverEntryPointQueryResult st;
        cudaGetDriverEntryPointByVersion("cuTensorMapEncodeTiled", (void**)&enc,
                                         12000, cudaEnableDefault, &st);
    }
    CUtensorMap mA{}, mB{};
    {
        cuuint64_t dims[3] = {DIN, TOKENS, 1};
        cuuint64_t str[2]  = {DIN * 2ull, (cuuint64_t)TOKENS * DIN * 2ull};
        cuuint32_t box[3]  = {64, 128, 1};
        cuuint32_t es[3]   = {1, 1, 1};
        enc(&mA, CU_TENSOR_MAP_DATA_TYPE_FLOAT16, 3, pa, dims, str, box, es,
            CU_TENSOR_MAP_INTERLEAVE_NONE, CU_TENSOR_MAP_SWIZZLE_128B,
            CU_TENSOR_MAP_L2_PROMOTION_L2_128B, CU_TENSOR_MAP_FLOAT_OOB_FILL_NONE);
    }
    {
        cuuint64_t dims[3] = {DIN, DOUT, 1};
        cuuint64_t str[2]  = {DIN * 2ull, (cuuint64_t)DOUT * DIN * 2ull};
        cuuint32_t box[3]  = {64, 256, 1};
        cuuint32_t es[3]   = {1, 1, 1};
        enc(&mB, CU_TENSOR_MAP_DATA_TYPE_FLOAT16, 3, pb, dims, str, box, es,
            CU_TENSOR_MAP_INTERLEAVE_NONE, CU_TENSOR_MAP_SWIZZLE_128B,
            CU_TENSOR_MAP_L2_PROMOTION_L2_128B, CU_TENSOR_MAP_FLOAT_OOB_FILL_NONE);
    }

    conv_all<<<XB + WB, 256>>>((const float4*)x, W);

    cudaFuncSetAttribute(gemm_persist, cudaFuncAttributeMaxDynamicSharedMemorySize, SMEM_BYTES);
    gemm_persist<<<NCTA, 256, SMEM_BYTES>>>(mA, mB, out);
}